// round 8
// baseline (speedup 1.0000x reference)
#include <cuda_runtime.h>
#include <cuda_fp16.h>
#include <cstdint>

// ---------------- problem constants ----------------
#define NQ      8
#define EMBED   512
#define FFN     2048
#define KC      128           // K-chunk over FFN
#define NCHUNK  16            // FFN / KC
#define THREADS 256
#define NCTAS   512           // 256 token tiles x 2 N-halves

// ---------------- smem layout (bytes) ----------------
#define SM_H    0             // 2 x 32768 : 128 rows x 256B fp16 (swizzled), double buffered
#define SM_B    65536         // 2 x 65536 : 256 rows x 256B fp16 (swizzled), double buffered
#define SM_Q    196608        // 128 rows x 16B fp16 (q, k-contig)
#define SMEM_TOTAL 198656

// fp16 scratch (allowed path: __device__ globals)
__device__ __half g_W2h[EMBED * FFN];
__device__ __half g_W1h[FFN * NQ];

// ---------------- helpers ----------------
__device__ __forceinline__ uint32_t smem_u32(const void* p) {
    uint32_t a;
    asm("{ .reg .u64 t; cvta.to.shared.u64 t, %1; cvt.u32.u64 %0, t; }" : "=r"(a) : "l"(p));
    return a;
}

#define CP_ASYNC_16(dst, src) \
    asm volatile("cp.async.cg.shared.global [%0], [%1], 16;" :: "r"((uint32_t)(dst)), "l"(src) : "memory")
#define CP_COMMIT() asm volatile("cp.async.commit_group;" ::: "memory")

#define LDSM_X4(r0, r1, r2, r3, addr) \
    asm volatile("ldmatrix.sync.aligned.m8n8.x4.shared.b16 {%0,%1,%2,%3}, [%4];" \
                 : "=r"(r0), "=r"(r1), "=r"(r2), "=r"(r3) : "r"(addr))
#define LDSM_X2(r0, r1, addr) \
    asm volatile("ldmatrix.sync.aligned.m8n8.x2.shared.b16 {%0,%1}, [%2];" \
                 : "=r"(r0), "=r"(r1) : "r"(addr))

// mma m16n8k16 row.col f32 += f16*f16
__device__ __forceinline__ void hmma16(float* d, const uint32_t* a, const uint32_t* b) {
    asm volatile("mma.sync.aligned.m16n8k16.row.col.f32.f16.f16.f32 "
                 "{%0,%1,%2,%3}, {%4,%5,%6,%7}, {%8,%9}, {%0,%1,%2,%3};"
                 : "+f"(d[0]), "+f"(d[1]), "+f"(d[2]), "+f"(d[3])
                 : "r"(a[0]), "r"(a[1]), "r"(a[2]), "r"(a[3]), "r"(b[0]), "r"(b[1]));
}
// mma m16n8k8 row.col f32 += f16*f16  (for h = relu(q . W1^T), K=8)
__device__ __forceinline__ void hmma8(float* d, const uint32_t* a, uint32_t b) {
    asm volatile("mma.sync.aligned.m16n8k8.row.col.f32.f16.f16.f32 "
                 "{%0,%1,%2,%3}, {%4,%5}, {%6}, {%0,%1,%2,%3};"
                 : "+f"(d[0]), "+f"(d[1]), "+f"(d[2]), "+f"(d[3])
                 : "r"(a[0]), "r"(a[1]), "r"(b));
}

__device__ __forceinline__ uint32_t relu_h2(float a, float b) {
    __half2 h = __floats2half2_rn(fmaxf(a, 0.f), fmaxf(b, 0.f));
    return *reinterpret_cast<uint32_t*>(&h);
}

// ---------------- W2 / W1 fp32 -> fp16 ----------------
__global__ void __launch_bounds__(256) wcvt_kernel(const float* __restrict__ W2,
                                                   const float* __restrict__ W1) {
    size_t i = ((size_t)blockIdx.x * blockDim.x + threadIdx.x) * 4;
    float4 v = *reinterpret_cast<const float4*>(W2 + i);
    __half2* d = reinterpret_cast<__half2*>(g_W2h + i);
    d[0] = __floats2half2_rn(v.x, v.y);
    d[1] = __floats2half2_rn(v.z, v.w);
    if (blockIdx.x < 16) {   // 16 blocks x 256 thr x 4 = 16384 = FFN*NQ
        size_t j = ((size_t)blockIdx.x * 256 + threadIdx.x) * 4;
        float4 w = *reinterpret_cast<const float4*>(W1 + j);
        __half2* e = reinterpret_cast<__half2*>(g_W1h + j);
        e[0] = __floats2half2_rn(w.x, w.y);
        e[1] = __floats2half2_rn(w.z, w.w);
    }
}

// ---------------- fused main kernel ----------------
__global__ void __launch_bounds__(THREADS, 1)
ffq_mma(const float* __restrict__ x, const float* __restrict__ theta,
        float* __restrict__ out) {
    extern __shared__ char smem[];
    const uint32_t sb = smem_u32(smem);
    const int tid   = threadIdx.x;
    const int lane  = tid & 31;
    const int warp  = tid >> 5;
    const int tile  = blockIdx.x >> 1;
    const int nhalf = blockIdx.x & 1;

    // MMA identity: 8 warps as 2(M) x 4(N), warp tile 64x64
    const int mrow0 = (warp & 1) * 64;
    const int n0    = (warp >> 1) * 64;
    // h-MMA identity: warps split f: fg = warp (16 f each)
    const int fg = warp;

    // ---- kick off cp.async for B chunk 0 ASAP ----
    {
        const char* src = (const char*)g_W2h + ((size_t)(nhalf * 256 + tid) * FFN) * 2;
        uint32_t dstrow = sb + SM_B + tid * 256;
        uint32_t sw = (tid & 15) << 4;
        #pragma unroll
        for (int cc = 0; cc < 16; cc++)
            CP_ASYNC_16(dstrow + ((cc * 16) ^ sw), src + cc * 16);
        CP_COMMIT();
    }

    // ---- quantum features -> smem (q[128][8] fp16, 16B rows) ----
    {
        int tok = tid >> 1, hf = tid & 1;
        const float* xp = x + ((size_t)tile * 128 + tok) * EMBED + hf * 4;
        float4 v  = *reinterpret_cast<const float4*>(xp);
        float4 tv = *reinterpret_cast<const float4*>(theta + hf * 4);
        uint32_t u0 = 0, u1 = 0;
        {
            __half2 a = __floats2half2_rn(cosf(2.f * v.x + tv.x), cosf(2.f * v.y + tv.y));
            __half2 b = __floats2half2_rn(cosf(2.f * v.z + tv.z), cosf(2.f * v.w + tv.w));
            u0 = *reinterpret_cast<uint32_t*>(&a);
            u1 = *reinterpret_cast<uint32_t*>(&b);
        }
        asm volatile("st.shared.v2.b32 [%0], {%1,%2};"
                     :: "r"(sb + SM_Q + tok * 16 + hf * 8), "r"(u0), "r"(u1) : "memory");
    }
    __syncthreads();

    // ---- load resident q fragments: A of m16n8k8 per m-tile (8 tiles x 2 regs) ----
    uint32_t aq[8][2];
    {
        uint32_t addr = sb + SM_Q + ((lane & 15)) * 16;
        #pragma unroll
        for (int mt = 0; mt < 8; mt++)
            LDSM_X2(aq[mt][0], aq[mt][1], addr + mt * 256);
    }

    // ---- W1 fragment prefetch for chunk 0 (2 LDG.b32 per lane) ----
    // lane T holds {W1h[f][2(T%4)], W1h[f][2(T%4)+1]} with f = k*128 + fg*16 + j*8 + T/4
    const char* w1base = (const char*)g_W1h + (size_t)(fg * 16 + (lane >> 2)) * 16 + (lane & 3) * 4;
    uint32_t w1c0 = *reinterpret_cast<const uint32_t*>(w1base);
    uint32_t w1c1 = *reinterpret_cast<const uint32_t*>(w1base + 128);

    // accumulators: 4 m16 x 8 n8 x 4 f32 = 128 regs
    float acc[4][8][4];
    #pragma unroll
    for (int mb = 0; mb < 4; mb++)
        #pragma unroll
        for (int nb = 0; nb < 8; nb++)
            #pragma unroll
            for (int i = 0; i < 4; i++) acc[mb][nb][i] = 0.0f;

    // per-lane ldmatrix address constants
    const int rowA = (lane & 7) + ((lane >> 3) & 1) * 8;   // A: mats m0-7/klo, m8-15/klo, m0-7/khi, m8-15/khi
    const int khA  = lane >> 4;
    const int rowB = (lane & 7) + ((lane >> 4) & 1) * 8;   // B: mats n0-7/klo, n0-7/khi, n8-15/klo, n8-15/khi
    const int khB  = (lane >> 3) & 1;
    const uint32_t swA = (uint32_t)rowA << 4;
    const uint32_t swB = (uint32_t)rowB << 4;
    // h-store constants (C frag of m16n8: c0c1 @ (T/4, 2(T%4)), c2c3 @ (+8 rows))
    const int hr0  = lane >> 2;
    const uint32_t hcb = (uint32_t)(fg * 32 + (lane & 3) * 4);

    for (int k = 0; k < NCHUNK; k++) {
        const int s = k & 1;
        const uint32_t hbuf = sb + SM_H + s * 32768;
        const uint32_t bbuf = sb + SM_B + s * 65536;

        // ---- h chunk via tensor cores: 8 m-tiles x 2 n8(f) tiles, k=8 ----
        #pragma unroll
        for (int mt = 0; mt < 8; mt++) {
            float h0[4] = {0.f, 0.f, 0.f, 0.f};
            float h1[4] = {0.f, 0.f, 0.f, 0.f};
            hmma8(h0, aq[mt], w1c0);
            hmma8(h1, aq[mt], w1c1);
            int r0 = mt * 16 + hr0, r1 = r0 + 8;
            uint32_t sw0 = (uint32_t)(r0 & 15) << 4, sw1 = (uint32_t)(r1 & 15) << 4;
            asm volatile("st.shared.b32 [%0], %1;" :: "r"(hbuf + r0 * 256 + (hcb ^ sw0)),        "r"(relu_h2(h0[0], h0[1])) : "memory");
            asm volatile("st.shared.b32 [%0], %1;" :: "r"(hbuf + r1 * 256 + (hcb ^ sw1)),        "r"(relu_h2(h0[2], h0[3])) : "memory");
            asm volatile("st.shared.b32 [%0], %1;" :: "r"(hbuf + r0 * 256 + ((hcb + 16) ^ sw0)), "r"(relu_h2(h1[0], h1[1])) : "memory");
            asm volatile("st.shared.b32 [%0], %1;" :: "r"(hbuf + r1 * 256 + ((hcb + 16) ^ sw1)), "r"(relu_h2(h1[2], h1[3])) : "memory");
        }

        // ---- prefetch W1 frags for chunk k+1 ----
        if (k + 1 < NCHUNK) {
            w1c0 = *reinterpret_cast<const uint32_t*>(w1base + (size_t)(k + 1) * 2048);
            w1c1 = *reinterpret_cast<const uint32_t*>(w1base + (size_t)(k + 1) * 2048 + 128);
        }

        // barrier #1: all warps done with big-MMA(k-1) (B[s^1] free) + H(k) visible
        __syncthreads();

        // ---- issue cp.async for B chunk k+1 into slot s^1 ----
        if (k + 1 < NCHUNK) {
            const char* src = (const char*)g_W2h +
                ((size_t)(nhalf * 256 + tid) * FFN + (size_t)(k + 1) * KC) * 2;
            uint32_t dstrow = sb + SM_B + (s ^ 1) * 65536 + tid * 256;
            uint32_t sw = (tid & 15) << 4;
            #pragma unroll
            for (int cc = 0; cc < 16; cc++)
                CP_ASYNC_16(dstrow + ((cc * 16) ^ sw), src + cc * 16);
            CP_COMMIT();
            asm volatile("cp.async.wait_group 1;" ::: "memory");
        } else {
            asm volatile("cp.async.wait_group 0;" ::: "memory");
        }
        // barrier #2: B(k) fully arrived for all threads
        __syncthreads();

        // ---- big MMA: 8 k16 steps, ldmatrix fragments ----
        #pragma unroll
        for (int kk = 0; kk < 8; kk++) {
            const uint32_t cbA = (uint32_t)(kk * 32 + khA * 16);
            const uint32_t cbB = (uint32_t)(kk * 32 + khB * 16);
            uint32_t Bf[8][2];
            #pragma unroll
            for (int j = 0; j < 4; j++) {
                uint32_t addr = bbuf + (uint32_t)(n0 + j * 16 + rowB) * 256 + (cbB ^ swB);
                LDSM_X4(Bf[2 * j][0], Bf[2 * j][1], Bf[2 * j + 1][0], Bf[2 * j + 1][1], addr);
            }
            #pragma unroll
            for (int mb = 0; mb < 4; mb++) {
                uint32_t A[4];
                uint32_t addr = hbuf + (uint32_t)(mrow0 + mb * 16 + rowA) * 256 + (cbA ^ swA);
                LDSM_X4(A[0], A[1], A[2], A[3], addr);
                #pragma unroll
                for (int nb = 0; nb < 8; nb++)
                    hmma16(acc[mb][nb], A, Bf[nb]);
            }
        }
    }

    // ---- epilogue ----
    #pragma unroll
    for (int mb = 0; mb < 4; mb++) {
        int r = mrow0 + mb * 16 + (lane >> 2);
        size_t gt = (size_t)tile * 128 + r;
        float* row0 = out + gt * EMBED + nhalf * 256;
        float* row1 = row0 + 8 * EMBED;
        #pragma unroll
        for (int nb = 0; nb < 8; nb++) {
            int c = n0 + nb * 8 + (lane & 3) * 2;
            *reinterpret_cast<float2*>(row0 + c) = make_float2(acc[mb][nb][0], acc[mb][nb][1]);
            *reinterpret_cast<float2*>(row1 + c) = make_float2(acc[mb][nb][2], acc[mb][nb][3]);
        }
    }
}

// ---------------- launch ----------------
extern "C" void kernel_launch(void* const* d_in, const int* in_sizes, int n_in,
                              void* d_out, int out_size) {
    const float* x     = (const float*)d_in[0];
    const float* theta = (const float*)d_in[1];
    const float* W1    = (const float*)d_in[2];
    const float* W2    = (const float*)d_in[3];
    float* out = (float*)d_out;

    cudaFuncSetAttribute(ffq_mma, cudaFuncAttributeMaxDynamicSharedMemorySize, SMEM_TOTAL);

    // W2/W1 fp32 -> fp16 scratch (deterministic each call)
    wcvt_kernel<<<(EMBED * FFN) / (256 * 4), 256>>>(W2, W1);

    // fused GEMM: 512 CTAs = 256 token tiles x 2 N-halves
    ffq_mma<<<NCTAS, THREADS, SMEM_TOTAL>>>(x, theta, out);
}

// round 9
// speedup vs baseline: 2.0934x; 2.0934x over previous
#include <cuda_runtime.h>
#include <cuda_fp16.h>
#include <cstdint>

// ---------------- problem constants ----------------
#define NQ      8
#define EMBED   512
#define FFN     2048
#define KC      64            // K-chunk over FFN
#define NCHUNK  32            // FFN / KC
#define THREADS 256
#define NCTAS   1024          // 256 token tiles x 4 N-quarters

// ---------------- smem layout (bytes) ----------------
#define SM_B    0             // 3 x 16384 : 128 rows x 128B fp16 (swizzled), 3-stage ring
#define SM_Q    49152         // 128 rows x 16B fp16 (q, k-contig)
#define SMEM_TOTAL 51200

// fp16 scratch (allowed path: __device__ globals)
__device__ __half g_W2h[EMBED * FFN];
__device__ __half g_W1h[FFN * NQ];

// ---------------- helpers ----------------
__device__ __forceinline__ uint32_t smem_u32(const void* p) {
    uint32_t a;
    asm("{ .reg .u64 t; cvta.to.shared.u64 t, %1; cvt.u32.u64 %0, t; }" : "=r"(a) : "l"(p));
    return a;
}

#define CP_ASYNC_16(dst, src) \
    asm volatile("cp.async.cg.shared.global [%0], [%1], 16;" :: "r"((uint32_t)(dst)), "l"(src) : "memory")
#define CP_COMMIT() asm volatile("cp.async.commit_group;" ::: "memory")

#define LDSM_X4(r0, r1, r2, r3, addr) \
    asm volatile("ldmatrix.sync.aligned.m8n8.x4.shared.b16 {%0,%1,%2,%3}, [%4];" \
                 : "=r"(r0), "=r"(r1), "=r"(r2), "=r"(r3) : "r"(addr))
#define LDSM_X2(r0, r1, addr) \
    asm volatile("ldmatrix.sync.aligned.m8n8.x2.shared.b16 {%0,%1}, [%2];" \
                 : "=r"(r0), "=r"(r1) : "r"(addr))

// mma m16n8k16 row.col f32 += f16*f16
__device__ __forceinline__ void hmma16(float* d, const uint32_t* a, const uint32_t* b) {
    asm volatile("mma.sync.aligned.m16n8k16.row.col.f32.f16.f16.f32 "
                 "{%0,%1,%2,%3}, {%4,%5,%6,%7}, {%8,%9}, {%0,%1,%2,%3};"
                 : "+f"(d[0]), "+f"(d[1]), "+f"(d[2]), "+f"(d[3])
                 : "r"(a[0]), "r"(a[1]), "r"(a[2]), "r"(a[3]), "r"(b[0]), "r"(b[1]));
}
// mma m16n8k8 row.col f32 += f16*f16  (h = relu(q . W1^T), K=8) — C=0 start
__device__ __forceinline__ void hmma8z(float* d, const uint32_t* a, uint32_t b) {
    asm volatile("mma.sync.aligned.m16n8k8.row.col.f32.f16.f16.f32 "
                 "{%0,%1,%2,%3}, {%4,%5}, {%6}, {%7,%7,%7,%7};"
                 : "=f"(d[0]), "=f"(d[1]), "=f"(d[2]), "=f"(d[3])
                 : "r"(a[0]), "r"(a[1]), "r"(b), "f"(0.0f));
}

__device__ __forceinline__ uint32_t relu_h2(float a, float b) {
    __half2 h = __floats2half2_rn(fmaxf(a, 0.f), fmaxf(b, 0.f));
    return *reinterpret_cast<uint32_t*>(&h);
}

// ---------------- W2 / W1 fp32 -> fp16 ----------------
__global__ void __launch_bounds__(256) wcvt_kernel(const float* __restrict__ W2,
                                                   const float* __restrict__ W1) {
    size_t i = ((size_t)blockIdx.x * blockDim.x + threadIdx.x) * 4;
    float4 v = *reinterpret_cast<const float4*>(W2 + i);
    __half2* d = reinterpret_cast<__half2*>(g_W2h + i);
    d[0] = __floats2half2_rn(v.x, v.y);
    d[1] = __floats2half2_rn(v.z, v.w);
    if (blockIdx.x < 16) {   // 16 x 256 x 4 = 16384 = FFN*NQ
        size_t j = ((size_t)blockIdx.x * 256 + threadIdx.x) * 4;
        float4 w = *reinterpret_cast<const float4*>(W1 + j);
        __half2* e = reinterpret_cast<__half2*>(g_W1h + j);
        e[0] = __floats2half2_rn(w.x, w.y);
        e[1] = __floats2half2_rn(w.z, w.w);
    }
}

// ---------------- fused main kernel ----------------
__global__ void __launch_bounds__(THREADS, 2)
ffq_mma(const float* __restrict__ x, const float* __restrict__ theta,
        float* __restrict__ out) {
    extern __shared__ char smem[];
    const uint32_t sb = smem_u32(smem);
    const int tid   = threadIdx.x;
    const int lane  = tid & 31;
    const int warp  = tid >> 5;
    const int tile  = blockIdx.x >> 2;     // token tile (128 tokens)
    const int nq    = blockIdx.x & 3;      // embed quarter (128 cols)

    // warp layout: 4(M) x 2(N); warp tile 32(M) x 64(N)
    const int mrow0 = (warp & 3) * 32;
    const int n0w   = (warp >> 2) * 64;

    // ---- B ring: issue cp.async for chunks 0,1 ASAP ----
    const int brow  = tid >> 1;            // 0..127  (W2 row within quarter)
    const int bhalf = tid & 1;             // 64B half of the 128B row
    const char* w2row = (const char*)g_W2h +
        ((size_t)(nq * 128 + brow) * FFN) * 2 + bhalf * 64;
    const uint32_t bswr = (uint32_t)(brow & 7) << 4;
    const uint32_t bdst = sb + SM_B + brow * 128;
    #pragma unroll
    for (int p = 0; p < 2; p++) {
        const char* src = w2row + (size_t)p * (KC * 2);
        uint32_t d0 = bdst + p * 16384;
        #pragma unroll
        for (int i = 0; i < 4; i++) {
            uint32_t c = bhalf * 64 + i * 16;
            CP_ASYNC_16(d0 + (c ^ bswr), src + i * 16);
        }
        CP_COMMIT();
    }

    // ---- quantum features -> smem q[128][8] fp16 (16B rows) ----
    {
        int tok = tid >> 1, hf = tid & 1;
        const float* xp = x + ((size_t)tile * 128 + tok) * EMBED + hf * 4;
        float4 v  = *reinterpret_cast<const float4*>(xp);
        float4 tv = *reinterpret_cast<const float4*>(theta + hf * 4);
        __half2 a = __floats2half2_rn(cosf(2.f * v.x + tv.x), cosf(2.f * v.y + tv.y));
        __half2 b = __floats2half2_rn(cosf(2.f * v.z + tv.z), cosf(2.f * v.w + tv.w));
        uint32_t u0 = *reinterpret_cast<uint32_t*>(&a);
        uint32_t u1 = *reinterpret_cast<uint32_t*>(&b);
        asm volatile("st.shared.v2.b32 [%0], {%1,%2};"
                     :: "r"(sb + SM_Q + tok * 16 + hf * 8), "r"(u0), "r"(u1) : "memory");
    }
    __syncthreads();

    // ---- resident q A-frags (m16n8k8): warp's own 2 m-tiles ----
    uint32_t aq[2][2];
    {
        uint32_t addr = sb + SM_Q + (mrow0 + (lane & 15)) * 16;
        LDSM_X2(aq[0][0], aq[0][1], addr);
        LDSM_X2(aq[1][0], aq[1][1], addr + 256);
    }

    // W1 b-frag base: lane T covers (f = g*8 + T/4, q = 2(T%4), 2(T%4)+1)
    const char* w1base = (const char*)g_W1h + (size_t)(lane >> 2) * 16 + (lane & 3) * 4;

    // accumulators: 2 m16 x 8 n8 x 4 f32 = 64 regs
    float acc[2][8][4];
    #pragma unroll
    for (int mb = 0; mb < 2; mb++)
        #pragma unroll
        for (int nb = 0; nb < 8; nb++)
            #pragma unroll
            for (int i = 0; i < 4; i++) acc[mb][nb][i] = 0.0f;

    // ldmatrix B lane addressing (m16n8k16 B-frag via x4, non-trans)
    const int rowB = (lane & 7) + ((lane >> 4) & 1) * 8;
    const int khB  = (lane >> 3) & 1;

    for (int k = 0; k < NCHUNK; k++) {
        const uint32_t bbuf = sb + SM_B + (k % 3) * 16384;

        // own group-k copies done (pending <= 1)
        if (k < NCHUNK - 1) { asm volatile("cp.async.wait_group 1;" ::: "memory"); }
        else                { asm volatile("cp.async.wait_group 0;" ::: "memory"); }
        // all threads' group-k copies visible; chunk k-1 done (slot (k+2)%3 free)
        __syncthreads();

        // ---- issue cp.async for chunk k+2 into slot (k+2)%3 ----
        if (k + 2 < NCHUNK) {
            const char* src = w2row + (size_t)(k + 2) * (KC * 2);
            uint32_t d0 = bdst + ((k + 2) % 3) * 16384;
            #pragma unroll
            for (int i = 0; i < 4; i++) {
                uint32_t c = bhalf * 64 + i * 16;
                CP_ASYNC_16(d0 + (c ^ bswr), src + i * 16);
            }
            CP_COMMIT();
        }

        // ---- W1 b-frags for this chunk: 8 f-groups of 8 ----
        uint32_t w1f[8];
        #pragma unroll
        for (int g = 0; g < 8; g++)
            w1f[g] = *reinterpret_cast<const uint32_t*>(
                w1base + ((size_t)k * KC + g * 8) * 16);

        // ---- 4 k16 steps ----
        #pragma unroll
        for (int kk = 0; kk < 4; kk++) {
            // B frags: 4 n16-tiles via ldmatrix
            uint32_t Bf[8][2];
            #pragma unroll
            for (int j = 0; j < 4; j++) {
                int r = n0w + j * 16 + rowB;
                uint32_t addr = bbuf + (uint32_t)r * 128 +
                                (((uint32_t)(kk * 32 + khB * 16)) ^ ((uint32_t)(r & 7) << 4));
                LDSM_X4(Bf[2 * j][0], Bf[2 * j][1], Bf[2 * j + 1][0], Bf[2 * j + 1][1], addr);
            }
            // A frags built in-register from h-MMA (C-frag == A-frag layout)
            #pragma unroll
            for (int mb = 0; mb < 2; mb++) {
                float h0[4], h1[4];
                hmma8z(h0, aq[mb], w1f[2 * kk]);
                hmma8z(h1, aq[mb], w1f[2 * kk + 1]);
                uint32_t A[4];
                A[0] = relu_h2(h0[0], h0[1]);
                A[1] = relu_h2(h0[2], h0[3]);
                A[2] = relu_h2(h1[0], h1[1]);
                A[3] = relu_h2(h1[2], h1[3]);
                #pragma unroll
                for (int nb = 0; nb < 8; nb++)
                    hmma16(acc[mb][nb], A, Bf[nb]);
            }
        }
    }

    // ---- epilogue ----
    #pragma unroll
    for (int mb = 0; mb < 2; mb++) {
        int r = mrow0 + mb * 16 + (lane >> 2);
        size_t gt = (size_t)tile * 128 + r;
        float* row0 = out + gt * EMBED + nq * 128 + n0w;
        float* row1 = row0 + 8 * EMBED;
        #pragma unroll
        for (int nb = 0; nb < 8; nb++) {
            int c = nb * 8 + (lane & 3) * 2;
            *reinterpret_cast<float2*>(row0 + c) = make_float2(acc[mb][nb][0], acc[mb][nb][1]);
            *reinterpret_cast<float2*>(row1 + c) = make_float2(acc[mb][nb][2], acc[mb][nb][3]);
        }
    }
}

// ---------------- launch ----------------
extern "C" void kernel_launch(void* const* d_in, const int* in_sizes, int n_in,
                              void* d_out, int out_size) {
    const float* x     = (const float*)d_in[0];
    const float* theta = (const float*)d_in[1];
    const float* W1    = (const float*)d_in[2];
    const float* W2    = (const float*)d_in[3];
    float* out = (float*)d_out;

    cudaFuncSetAttribute(ffq_mma, cudaFuncAttributeMaxDynamicSharedMemorySize, SMEM_TOTAL);

    // W2/W1 fp32 -> fp16 scratch (deterministic each call)
    wcvt_kernel<<<(EMBED * FFN) / (256 * 4), 256>>>(W2, W1);

    // fused GEMM: 1024 CTAs = 256 token tiles x 4 N-quarters, 2 CTAs/SM
    ffq_mma<<<NCTAS, THREADS, SMEM_TOTAL>>>(x, theta, out);
}

// round 11
// speedup vs baseline: 2.2252x; 1.0629x over previous
#include <cuda_runtime.h>
#include <cuda_fp16.h>
#include <cstdint>

// ---------------- problem constants ----------------
#define NQ      8
#define EMBED   512
#define FFN     2048
#define KC      64            // K-chunk over FFN
#define NCHUNK  32            // FFN / KC
#define THREADS 256
#define NCTAS   1024          // 256 token tiles x 4 N-quarters

// ---------------- smem layout (bytes) ----------------
#define SM_B    0             // 3 x 16384 : 128 rows x 128B fp16 (swizzled), 3-stage ring
#define SM_Q    49152         // 128 rows x 16B fp16 (q, k-contig)
#define SMEM_TOTAL 51200

// fp16 scratch (allowed path: __device__ globals)
__device__ __half g_W2h[EMBED * FFN];
__device__ __half g_W1h[FFN * NQ];

// ---------------- helpers ----------------
__device__ __forceinline__ uint32_t smem_u32(const void* p) {
    uint32_t a;
    asm("{ .reg .u64 t; cvta.to.shared.u64 t, %1; cvt.u32.u64 %0, t; }" : "=r"(a) : "l"(p));
    return a;
}

#define CP_ASYNC_16(dst, src) \
    asm volatile("cp.async.cg.shared.global [%0], [%1], 16;" :: "r"((uint32_t)(dst)), "l"(src) : "memory")
#define CP_COMMIT() asm volatile("cp.async.commit_group;" ::: "memory")

#define LDSM_X4(r0, r1, r2, r3, addr) \
    asm volatile("ldmatrix.sync.aligned.m8n8.x4.shared.b16 {%0,%1,%2,%3}, [%4];" \
                 : "=r"(r0), "=r"(r1), "=r"(r2), "=r"(r3) : "r"(addr))
#define LDSM_X2(r0, r1, addr) \
    asm volatile("ldmatrix.sync.aligned.m8n8.x2.shared.b16 {%0,%1}, [%2];" \
                 : "=r"(r0), "=r"(r1) : "r"(addr))

// mma m16n8k16 row.col f32 += f16*f16
__device__ __forceinline__ void hmma16(float* d, const uint32_t* a, const uint32_t* b) {
    asm volatile("mma.sync.aligned.m16n8k16.row.col.f32.f16.f16.f32 "
                 "{%0,%1,%2,%3}, {%4,%5,%6,%7}, {%8,%9}, {%0,%1,%2,%3};"
                 : "+f"(d[0]), "+f"(d[1]), "+f"(d[2]), "+f"(d[3])
                 : "r"(a[0]), "r"(a[1]), "r"(a[2]), "r"(a[3]), "r"(b[0]), "r"(b[1]));
}
// mma m16n8k8 row.col f32 += f16*f16  (h = relu(q . W1^T), K=8) — C=0 start
__device__ __forceinline__ void hmma8z(float* d, const uint32_t* a, uint32_t b) {
    asm volatile("mma.sync.aligned.m16n8k8.row.col.f32.f16.f16.f32 "
                 "{%0,%1,%2,%3}, {%4,%5}, {%6}, {%7,%7,%7,%7};"
                 : "=f"(d[0]), "=f"(d[1]), "=f"(d[2]), "=f"(d[3])
                 : "r"(a[0]), "r"(a[1]), "r"(b), "f"(0.0f));
}

// pack two f32 to f16x2, relu via max.f16x2 (1 ALU op)
__device__ __forceinline__ uint32_t prelu_h2(float a, float b) {
    __half2 h = __floats2half2_rn(a, b);
    uint32_t u = *reinterpret_cast<uint32_t*>(&h);
    asm("max.f16x2 %0, %0, %1;" : "+r"(u) : "r"(0u));
    return u;
}

// compute A-frags (m16n8k16 A layout) for one k16-step from q and two W1 b-frags
__device__ __forceinline__ void compute_A(uint32_t A[2][4], const uint32_t aq[2][2],
                                          uint32_t w1lo, uint32_t w1hi) {
    #pragma unroll
    for (int mb = 0; mb < 2; mb++) {
        float h0[4], h1[4];
        hmma8z(h0, aq[mb], w1lo);
        hmma8z(h1, aq[mb], w1hi);
        A[mb][0] = prelu_h2(h0[0], h0[1]);
        A[mb][1] = prelu_h2(h0[2], h0[3]);
        A[mb][2] = prelu_h2(h1[0], h1[1]);
        A[mb][3] = prelu_h2(h1[2], h1[3]);
    }
}

// ---------------- W2 / W1 fp32 -> fp16 ----------------
__global__ void __launch_bounds__(256) wcvt_kernel(const float* __restrict__ W2,
                                                   const float* __restrict__ W1) {
    size_t i = ((size_t)blockIdx.x * blockDim.x + threadIdx.x) * 4;
    float4 v = *reinterpret_cast<const float4*>(W2 + i);
    __half2* d = reinterpret_cast<__half2*>(g_W2h + i);
    d[0] = __floats2half2_rn(v.x, v.y);
    d[1] = __floats2half2_rn(v.z, v.w);
    if (blockIdx.x < 16) {   // 16 x 256 x 4 = 16384 = FFN*NQ
        size_t j = ((size_t)blockIdx.x * 256 + threadIdx.x) * 4;
        float4 w = *reinterpret_cast<const float4*>(W1 + j);
        __half2* e = reinterpret_cast<__half2*>(g_W1h + j);
        e[0] = __floats2half2_rn(w.x, w.y);
        e[1] = __floats2half2_rn(w.z, w.w);
    }
}

// ---------------- fused main kernel ----------------
__global__ void __launch_bounds__(THREADS, 2)
ffq_mma(const float* __restrict__ x, const float* __restrict__ theta,
        float* __restrict__ out) {
    extern __shared__ char smem[];
    const uint32_t sb = smem_u32(smem);
    const int tid   = threadIdx.x;
    const int lane  = tid & 31;
    const int warp  = tid >> 5;
    const int tile  = blockIdx.x >> 2;     // token tile (128 tokens)
    const int nq    = blockIdx.x & 3;      // embed quarter (128 cols)

    // warp layout: 4(M) x 2(N); warp tile 32(M) x 64(N)
    const int mrow0 = (warp & 3) * 32;
    const int n0w   = (warp >> 2) * 64;

    // ---- B ring: issue cp.async for chunks 0,1 ASAP ----
    const int brow  = tid >> 1;            // 0..127  (W2 row within quarter)
    const int bhalf = tid & 1;             // 64B half of the 128B row
    const char* w2row = (const char*)g_W2h +
        ((size_t)(nq * 128 + brow) * FFN) * 2 + bhalf * 64;
    const uint32_t bswr = (uint32_t)(brow & 7) << 4;
    const uint32_t bdst = sb + SM_B + brow * 128;
    #pragma unroll
    for (int p = 0; p < 2; p++) {
        const char* src = w2row + (size_t)p * (KC * 2);
        uint32_t d0 = bdst + p * 16384;
        #pragma unroll
        for (int i = 0; i < 4; i++) {
            uint32_t c = bhalf * 64 + i * 16;
            CP_ASYNC_16(d0 + (c ^ bswr), src + i * 16);
        }
        CP_COMMIT();
    }

    // ---- quantum features -> smem q[128][8] fp16 (16B rows) ----
    {
        int tok = tid >> 1, hf = tid & 1;
        const float* xp = x + ((size_t)tile * 128 + tok) * EMBED + hf * 4;
        float4 v  = *reinterpret_cast<const float4*>(xp);
        float4 tv = *reinterpret_cast<const float4*>(theta + hf * 4);
        __half2 a = __floats2half2_rn(cosf(2.f * v.x + tv.x), cosf(2.f * v.y + tv.y));
        __half2 b = __floats2half2_rn(cosf(2.f * v.z + tv.z), cosf(2.f * v.w + tv.w));
        uint32_t u0 = *reinterpret_cast<uint32_t*>(&a);
        uint32_t u1 = *reinterpret_cast<uint32_t*>(&b);
        asm volatile("st.shared.v2.b32 [%0], {%1,%2};"
                     :: "r"(sb + SM_Q + tok * 16 + hf * 8), "r"(u0), "r"(u1) : "memory");
    }
    __syncthreads();

    // ---- resident q A-frags (m16n8k8): warp's own 2 m-tiles ----
    uint32_t aq[2][2];
    {
        uint32_t addr = sb + SM_Q + (mrow0 + (lane & 15)) * 16;
        LDSM_X2(aq[0][0], aq[0][1], addr);
        LDSM_X2(aq[1][0], aq[1][1], addr + 256);
    }

    // W1 b-frag base: lane T covers (f = g*8 + T/4, q = 2(T%4), 2(T%4)+1)
    const char* w1base = (const char*)g_W1h + (size_t)(lane >> 2) * 16 + (lane & 3) * 4;

    // accumulators: 2 m16 x 8 n8 x 4 f32 = 64 regs
    float acc[2][8][4];
    #pragma unroll
    for (int mb = 0; mb < 2; mb++)
        #pragma unroll
        for (int nb = 0; nb < 8; nb++)
            #pragma unroll
            for (int i = 0; i < 4; i++) acc[mb][nb][i] = 0.0f;

    // ldmatrix B lane addressing (m16n8k16 B-frag via x4, non-trans)
    const int rowB = (lane & 7) + ((lane >> 4) & 1) * 8;
    const int khB  = (lane >> 3) & 1;

    // ---- W1 frags + A-frags for chunk 0, steps 0..1 (pre-barrier tensor work) ----
    uint32_t w1f[8];
    #pragma unroll
    for (int g = 0; g < 8; g++)
        w1f[g] = *reinterpret_cast<const uint32_t*>(w1base + (size_t)(g * 8) * 16);

    uint32_t A01[2][2][4];   // steps 0,1
    compute_A(A01[0], aq, w1f[0], w1f[1]);
    compute_A(A01[1], aq, w1f[2], w1f[3]);

    for (int k = 0; k < NCHUNK; k++) {
        const uint32_t bbuf = sb + SM_B + (k % 3) * 16384;

        // own group-k copies done (pending <= 1)
        if (k < NCHUNK - 1) { asm volatile("cp.async.wait_group 1;" ::: "memory"); }
        else                { asm volatile("cp.async.wait_group 0;" ::: "memory"); }
        // all threads' group-k copies visible; chunk k-1 done (slot (k+2)%3 free)
        __syncthreads();

        // ---- issue cp.async for chunk k+2 into slot (k+2)%3 ----
        if (k + 2 < NCHUNK) {
            const char* src = w2row + (size_t)(k + 2) * (KC * 2);
            uint32_t d0 = bdst + ((k + 2) % 3) * 16384;
            #pragma unroll
            for (int i = 0; i < 4; i++) {
                uint32_t c = bhalf * 64 + i * 16;
                CP_ASYNC_16(d0 + (c ^ bswr), src + i * 16);
            }
            CP_COMMIT();
        }

        // ---- steps 0,1: pure LDSM + HMMA (A already resident) ----
        #pragma unroll
        for (int kk = 0; kk < 2; kk++) {
            uint32_t Bf[8][2];
            #pragma unroll
            for (int j = 0; j < 4; j++) {
                int r = n0w + j * 16 + rowB;
                uint32_t addr = bbuf + (uint32_t)r * 128 +
                                (((uint32_t)(kk * 32 + khB * 16)) ^ ((uint32_t)(r & 7) << 4));
                LDSM_X4(Bf[2 * j][0], Bf[2 * j][1], Bf[2 * j + 1][0], Bf[2 * j + 1][1], addr);
            }
            #pragma unroll
            for (int mb = 0; mb < 2; mb++)
                #pragma unroll
                for (int nb = 0; nb < 8; nb++)
                    hmma16(acc[mb][nb], A01[kk][mb], Bf[nb]);
        }

        // ---- A-frags for steps 2,3 (independent hmma8 batch) ----
        uint32_t A23[2][2][4];
        compute_A(A23[0], aq, w1f[4], w1f[5]);
        compute_A(A23[1], aq, w1f[6], w1f[7]);

        // ---- steps 2,3 ----
        #pragma unroll
        for (int kk = 2; kk < 4; kk++) {
            uint32_t Bf[8][2];
            #pragma unroll
            for (int j = 0; j < 4; j++) {
                int r = n0w + j * 16 + rowB;
                uint32_t addr = bbuf + (uint32_t)r * 128 +
                                (((uint32_t)(kk * 32 + khB * 16)) ^ ((uint32_t)(r & 7) << 4));
                LDSM_X4(Bf[2 * j][0], Bf[2 * j][1], Bf[2 * j + 1][0], Bf[2 * j + 1][1], addr);
            }
            #pragma unroll
            for (int mb = 0; mb < 2; mb++)
                #pragma unroll
                for (int nb = 0; nb < 8; nb++)
                    hmma16(acc[mb][nb], A23[kk - 2][mb], Bf[nb]);
        }

        // ---- prep next chunk: W1 frags + A(0,1), overlapping hmma16 tail ----
        if (k + 1 < NCHUNK) {
            #pragma unroll
            for (int g = 0; g < 8; g++)
                w1f[g] = *reinterpret_cast<const uint32_t*>(
                    w1base + ((size_t)(k + 1) * KC + g * 8) * 16);
            compute_A(A01[0], aq, w1f[0], w1f[1]);
            compute_A(A01[1], aq, w1f[2], w1f[3]);
        }
    }

    // ---- epilogue ----
    #pragma unroll
    for (int mb = 0; mb < 2; mb++) {
        int r = mrow0 + mb * 16 + (lane >> 2);
        size_t gt = (size_t)tile * 128 + r;
        float* row0 = out + gt * EMBED + nq * 128 + n0w;
        float* row1 = row0 + 8 * EMBED;
        #pragma unroll
        for (int nb = 0; nb < 8; nb++) {
            int c = nb * 8 + (lane & 3) * 2;
            *reinterpret_cast<float2*>(row0 + c) = make_float2(acc[mb][nb][0], acc[mb][nb][1]);
            *reinterpret_cast<float2*>(row1 + c) = make_float2(acc[mb][nb][2], acc[mb][nb][3]);
        }
    }
}

// ---------------- launch ----------------
extern "C" void kernel_launch(void* const* d_in, const int* in_sizes, int n_in,
                              void* d_out, int out_size) {
    const float* x     = (const float*)d_in[0];
    const float* theta = (const float*)d_in[1];
    const float* W1    = (const float*)d_in[2];
    const float* W2    = (const float*)d_in[3];
    float* out = (float*)d_out;

    cudaFuncSetAttribute(ffq_mma, cudaFuncAttributeMaxDynamicSharedMemorySize, SMEM_TOTAL);

    // W2/W1 fp32 -> fp16 scratch (deterministic each call)
    wcvt_kernel<<<(EMBED * FFN) / (256 * 4), 256>>>(W2, W1);

    // fused GEMM: 1024 CTAs = 256 token tiles x 4 N-quarters, 2 CTAs/SM
    ffq_mma<<<NCTAS, THREADS, SMEM_TOTAL>>>(x, theta, out);
}